// round 14
// baseline (speedup 1.0000x reference)
#include <cuda_runtime.h>
#include <stdint.h>
#include <math.h>

#define HH   128
#define NHD  2
#define HDd  64
#define BB   8
#define LLs  200
#define TVC  32
#define NROWS (BB*LLs)   // 1600
#define KSTR 70          // attn smem row stride (floats): conflict-free
#define GRID 148

typedef unsigned long long ull;

// scratch (device globals: no allocation allowed)
__device__ float g_q  [NROWS*HH];
__device__ float g_kk [NROWS*HH];
__device__ float g_vv [NROWS*HH];
__device__ float g_ctx[NROWS*HH];

// grid-barrier counters (zero-initialized; reset at end of every launch)
__device__ unsigned g_bar1, g_bar2, g_bar3;

// ---- helpers --------------------------------------------------------------
__device__ __forceinline__ void cp16(uint32_t s, const void* g) {
    asm volatile("cp.async.cg.shared.global [%0], [%1], 16;" :: "r"(s), "l"(g));
}
__device__ __forceinline__ void cp_commit_wait() {
    asm volatile("cp.async.commit_group;");
    asm volatile("cp.async.wait_group 0;" ::: "memory");
}
__device__ __forceinline__ ull pk2(float x) {
    ull r; asm("mov.b64 %0,{%1,%1};" : "=l"(r) : "f"(x)); return r;
}
__device__ __forceinline__ void fma2(ull& d, ull a, ull b) {
    asm("fma.rn.f32x2 %0,%1,%2,%0;" : "+l"(d) : "l"(a), "l"(b));
}
__device__ __forceinline__ float f2lo(ull v) {
    float a, b; asm("mov.b64 {%0,%1},%2;" : "=f"(a), "=f"(b) : "l"(v)); return a;
}
__device__ __forceinline__ float f2hi(ull v) {
    float a, b; asm("mov.b64 {%0,%1},%2;" : "=f"(a), "=f"(b) : "l"(v)); return b;
}

__device__ __forceinline__ void grid_barrier(unsigned* ctr, unsigned target) {
    __syncthreads();
    if (threadIdx.x == 0) {
        __threadfence();
        atomicAdd(ctr, 1u);
        while (*(volatile unsigned*)ctr < target) __nanosleep(64);
        __threadfence();
    }
    __syncthreads();
}

extern __shared__ float smem_dyn[];

// attn smem footprint (floats) — also the kernel's total dynamic smem
#define SMEM_FLOATS 40736

// ---------------------------------------------------------------------------
// Fused persistent kernel: proj -> barrier -> attn -> barrier -> out+LN
// grid 148 x 256 threads, 1 block/SM (163KB smem) -> all blocks resident.
// ---------------------------------------------------------------------------
__global__ void __launch_bounds__(256, 1)
fused_kernel(const float* __restrict__ X,
             const void*  __restrict__ tsq,
             const float* __restrict__ maskg,
             const float* __restrict__ Wq, const float* __restrict__ bq,
             const float* __restrict__ Wk, const float* __restrict__ bk,
             const float* __restrict__ Wv, const float* __restrict__ bv,
             const float* __restrict__ Wd, const float* __restrict__ bd,
             const float* __restrict__ lng, const float* __restrict__ lnb,
             const float* __restrict__ KTg, const float* __restrict__ VTg,
             const float* __restrict__ kpos, const float* __restrict__ vpos,
             float* __restrict__ out)
{
    const int bid  = blockIdx.x;
    const int tid  = threadIdx.x;
    const int lane = tid & 31;
    const int wid  = tid >> 5;
    float* sm = smem_dyn;

    // ========================= PHASE 1: QKV projection ======================
    // 300 units: unit = (m in 0..2, hf in 0..1, rowtile in 0..49), 32r x 64c
    for (int u = bid; u < 300; u += GRID) {
        const int m  = u / 100;
        const int r  = u % 100;
        const int hf = r / 50;
        const int rb = (r % 50) * 32;

        float* xs = sm;          // 32*128 = 4096
        float* ws = sm + 4096;   // 128*64 = 8192

        const float* W    = (m==0) ? Wq : (m==1 ? Wk : Wv);
        const float* bias = (m==0) ? bq : (m==1 ? bk : bv);

        {
            uint32_t xs_s = (uint32_t)__cvta_generic_to_shared(xs);
            uint32_t ws_s = (uint32_t)__cvta_generic_to_shared(ws);
            #pragma unroll
            for (int j = 0; j < 4; j++) {
                int c = tid + 256*j;
                cp16(xs_s + c*16, X + (size_t)rb*128 + c*4);
            }
            #pragma unroll
            for (int j = 0; j < 8; j++) {
                int c = tid + 256*j;
                int i = c >> 4, sub = c & 15;
                cp16(ws_s + (i*64 + sub*4)*4, W + i*128 + hf*64 + sub*4);
            }
            cp_commit_wait();
        }
        __syncthreads();

        const int r0 = wid * 4;
        ull a0=0, a1=0, a2=0, a3=0;
        const ull* wsu = (const ull*)ws;

        for (int i0 = 0; i0 < 128; i0 += 4) {
            float4 xr0 = *(const float4*)(xs + (r0+0)*128 + i0);
            float4 xr1 = *(const float4*)(xs + (r0+1)*128 + i0);
            float4 xr2 = *(const float4*)(xs + (r0+2)*128 + i0);
            float4 xr3 = *(const float4*)(xs + (r0+3)*128 + i0);
            #define PSTEP(comp, j)                                            \
                {                                                             \
                    ull wv = wsu[(i0 + (j))*32 + lane];                       \
                    fma2(a0, pk2(xr0.comp), wv);                              \
                    fma2(a1, pk2(xr1.comp), wv);                              \
                    fma2(a2, pk2(xr2.comp), wv);                              \
                    fma2(a3, pk2(xr3.comp), wv);                              \
                }
            PSTEP(x, 0)
            PSTEP(y, 1)
            PSTEP(z, 2)
            PSTEP(w, 3)
            #undef PSTEP
        }

        const int col = hf*64 + lane*2;
        float2 bz = *(const float2*)(bias + col);
        float* outg = (m==0) ? g_q : (m==1 ? g_kk : g_vv);
        const float* pos = (m==1) ? kpos : vpos;

        ull acc[4] = {a0, a1, a2, a3};
        #pragma unroll
        for (int rr = 0; rr < 4; rr++) {
            const int gr = rb + r0 + rr;
            float2 o;
            o.x = f2lo(acc[rr]) + bz.x;
            o.y = f2hi(acc[rr]) + bz.y;
            if (m != 0) {
                float2 p = *(const float2*)(pos + (gr % LLs)*128 + col);
                o.x += p.x; o.y += p.y;
            }
            *(float2*)(outg + (size_t)gr*128 + col) = o;
        }
        __syncthreads();   // smem reuse across units
    }

    grid_barrier(&g_bar1, GRID);

    // ========================= PHASE 2: attention ===========================
    if (bid < 128) {
        const int qt = bid & 7;
        const int h  = (bid >> 3) & 1;
        const int b  = bid >> 4;

        float* kk    = sm;                   // 200*70
        float* vv    = sm + 14000;           // 200*70
        float* kt    = sm + 28000;           // 32*70
        float* vt    = sm + 30240;           // 32*70
        int*   tv    = (int*)(sm + 32480);   // 200
        float* qall  = sm + 32680;           // 25*64
        float* tsall = sm + 34280;           // 25*32
        float* pdA   = sm + 35080;           // 200 float4
        float* pdB   = sm + 35880;           // 200
        float* sdA   = sm + 36080;           // 200 float4
        float* sdB   = sm + 36880;           // 200
        int*   ix4   = (int*)(sm + 37080);   // 200 int4
        int*   ixb   = (int*)(sm + 37880);   // 200
        float* pA    = sm + 38080;           // 5*8*32 float2
        float* red   = sm + 40640;           // 96

        const float* kkg = g_kk + (size_t)(b*LLs)*HH + h*HDd;
        const float* vvg = g_vv + (size_t)(b*LLs)*HH + h*HDd;
        for (int idx = tid; idx < LLs*32; idx += 256) {
            int k = idx >> 5, d2 = idx & 31;
            ((float2*)(kk + k*KSTR))[d2] = ((const float2*)(kkg + k*HH))[d2];
            ((float2*)(vv + k*KSTR))[d2] = ((const float2*)(vvg + k*HH))[d2];
        }
        for (int idx = tid; idx < TVC*32; idx += 256) {
            int w = idx >> 5, d2 = idx & 31;
            ((float2*)(kt + w*KSTR))[d2] = ((const float2*)(KTg + w*HH + h*HDd))[d2];
            ((float2*)(vt + w*KSTR))[d2] = ((const float2*)(VTg + w*HH + h*HDd))[d2];
        }
        // time values: detect int64 vs int32 storage (word 199 is the high
        // word of element 99 if int64 -> 0; sorted max of row 0 if int32 -> >0)
        {
            const int* t32 = (const int*)tsq;
            bool is64 = (t32[199] == 0);
            for (int k = tid; k < LLs; k += 256)
                tv[k] = is64 ? (int)((const long long*)tsq)[b*LLs + k]
                             : t32[b*LLs + k];
        }
        {
            const float* qg = g_q + (size_t)(b*LLs)*HH + h*HDd;
            for (int idx = tid; idx < 25*16; idx += 256) {
                int q = idx >> 4, d4 = idx & 15;
                ((float4*)(qall + q*64))[d4] = ((const float4*)(qg + (qt*25+q)*HH))[d4];
            }
        }
        __syncthreads();

        for (int i = tid; i < 25*32; i += 256) {
            int q = i >> 5, w = i & 31;
            const ull* q2  = (const ull*)(qall + q*64);
            const ull* ktr = (const ull*)(kt + w*KSTR);
            ull a = 0;
            #pragma unroll
            for (int j = 0; j < 32; j++) fma2(a, q2[j], ktr[j]);
            tsall[i] = f2lo(a) + f2hi(a);
        }
        __syncthreads();

        for (int it = 0; it < 5; it++) {
            const int q0    = it*5;
            const int qbase = qt*25 + q0;

            float s[5], e[5];
            #pragma unroll
            for (int q = 0; q < 5; q++) { s[q] = -1e30f; e[q] = 0.f; }

            const int k = tid;
            if (k < LLs) {
                ull a2[5];
                #pragma unroll
                for (int q = 0; q < 5; q++) a2[q] = 0;

                const ull* kr = (const ull*)(kk + k*KSTR);
                #pragma unroll
                for (int j = 0; j < 32; j++) {
                    ull y = kr[j];
                    #pragma unroll
                    for (int q = 0; q < 5; q++) {
                        ull x = ((const ull*)(qall + (q0+q)*64))[j];
                        fma2(a2[q], x, y);
                    }
                }

                const int tk = tv[k];
                const float* mrow = maskg + ((size_t)(b*LLs) + qbase)*LLs + k;
                int ixs[5];
                #pragma unroll
                for (int q = 0; q < 5; q++) {
                    float aq = f2lo(a2[q]) + f2hi(a2[q]);
                    int dt = tv[qbase+q] - tk; if (dt < 0) dt = -dt;
                    int ixq = (int)log1pf((float)dt);
                    s[q] = (aq + tsall[(q0+q)*32 + ixq])*0.125f + mrow[q*LLs];
                    ixs[q] = ixq;
                }
                ((int4*)ix4)[k] = make_int4(ixs[0], ixs[1], ixs[2], ixs[3]);
                ixb[k] = ixs[4];
                ((float4*)sdA)[k] = make_float4(s[0], s[1], s[2], s[3]);
                sdB[k] = s[4];
                #pragma unroll
                for (int q = 0; q < 5; q++) e[q] = __expf(s[q]);
            }

            #pragma unroll
            for (int q = 0; q < 5; q++) {
                float se = e[q];
                #pragma unroll
                for (int o = 16; o > 0; o >>= 1)
                    se += __shfl_xor_sync(0xFFFFFFFFu, se, o);
                if (lane == 0) red[q*8 + wid] = se;
            }
            __syncthreads();
            if (tid < 5) {
                float se = 0.f;
                #pragma unroll
                for (int i = 0; i < 8; i++) se += red[tid*8 + i];
                red[48 + tid] = 1.f / se;
            }
            __syncthreads();

            if (k < LLs) {
                float4 p;
                p.x = e[0]*red[48]; p.y = e[1]*red[49];
                p.z = e[2]*red[50]; p.w = e[3]*red[51];
                ((float4*)pdA)[k] = p;
                pdB[k] = e[4]*red[52];
            }
            __syncthreads();

            {
                const int kc = wid, d2 = lane;
                float2 acc[5];
                #pragma unroll
                for (int q = 0; q < 5; q++) { acc[q].x = 0.f; acc[q].y = 0.f; }
                const int kb = kc*25;
                #pragma unroll 5
                for (int kk2 = 0; kk2 < 25; kk2++) {
                    int kx = kb + kk2;
                    float2 v  = *(const float2*)(vv + kx*KSTR + 2*d2);
                    int4   iv = ((const int4*)ix4)[kx];
                    int    i4 = ixb[kx];
                    float2 t0 = *(const float2*)(vt + iv.x*KSTR + 2*d2);
                    float2 t1 = *(const float2*)(vt + iv.y*KSTR + 2*d2);
                    float2 t2 = *(const float2*)(vt + iv.z*KSTR + 2*d2);
                    float2 t3 = *(const float2*)(vt + iv.w*KSTR + 2*d2);
                    float2 t4 = *(const float2*)(vt + i4*KSTR   + 2*d2);
                    float4 p4 = ((const float4*)pdA)[kx];
                    float  pb = pdB[kx];
                    float4 s4 = ((const float4*)sdA)[kx];
                    float  sb = sdB[kx];
                    acc[0].x += p4.x*v.x + s4.x*t0.x; acc[0].y += p4.x*v.y + s4.x*t0.y;
                    acc[1].x += p4.y*v.x + s4.y*t1.x; acc[1].y += p4.y*v.y + s4.y*t1.y;
                    acc[2].x += p4.z*v.x + s4.z*t2.x; acc[2].y += p4.z*v.y + s4.z*t2.y;
                    acc[3].x += p4.w*v.x + s4.w*t3.x; acc[3].y += p4.w*v.y + s4.w*t3.y;
                    acc[4].x += pb  *v.x + sb  *t4.x; acc[4].y += pb  *v.y + sb  *t4.y;
                }
                #pragma unroll
                for (int q = 0; q < 5; q++)
                    ((float2*)pA)[(q*8 + kc)*32 + d2] = acc[q];
            }
            __syncthreads();

            if (tid < 160) {
                int q = tid >> 5, d2 = tid & 31;
                float2 a; a.x = 0.f; a.y = 0.f;
                #pragma unroll
                for (int kc = 0; kc < 8; kc++) {
                    float2 x = ((float2*)pA)[(q*8 + kc)*32 + d2];
                    a.x += x.x; a.y += x.y;
                }
                *(float2*)(g_ctx + ((size_t)(b*LLs) + qbase + q)*HH + h*HDd + 2*d2) = a;
            }
            __syncthreads();
        }
    }

    grid_barrier(&g_bar2, GRID);

    // ========================= PHASE 3: out proj + LN =======================
    if (bid < 100) {
        const int rb = bid * 16;

        float* xs = sm;          // 16*128 = 2048
        float* ws = sm + 2048;   // 128*128 = 16384

        {
            uint32_t xs_s = (uint32_t)__cvta_generic_to_shared(xs);
            uint32_t ws_s = (uint32_t)__cvta_generic_to_shared(ws);
            #pragma unroll
            for (int j = 0; j < 2; j++) {
                int c = tid + 256*j;
                cp16(xs_s + c*16, g_ctx + (size_t)rb*128 + c*4);
            }
            #pragma unroll
            for (int j = 0; j < 16; j++) {
                int c = tid + 256*j;
                cp16(ws_s + c*16, Wd + c*4);
            }
            cp_commit_wait();
        }
        __syncthreads();

        const int r0 = wid * 2;
        ull a00=0, a01=0, a10=0, a11=0;
        const ulonglong2* ws2 = (const ulonglong2*)ws;

        for (int i0 = 0; i0 < 128; i0 += 4) {
            float4 xr0 = *(const float4*)(xs + (r0+0)*128 + i0);
            float4 xr1 = *(const float4*)(xs + (r0+1)*128 + i0);
            #define OSTEP(comp, j)                                            \
                {                                                             \
                    ulonglong2 wv = ws2[(i0 + (j))*32 + lane];                \
                    ull p0 = pk2(xr0.comp), p1 = pk2(xr1.comp);               \
                    fma2(a00, p0, wv.x); fma2(a01, p0, wv.y);                 \
                    fma2(a10, p1, wv.x); fma2(a11, p1, wv.y);                 \
                }
            OSTEP(x, 0)
            OSTEP(y, 1)
            OSTEP(z, 2)
            OSTEP(w, 3)
            #undef OSTEP
        }

        float4 bz = ((const float4*)bd)[lane];
        float4 g  = ((const float4*)lng)[lane];
        float4 bb = ((const float4*)lnb)[lane];

        ull aL[2] = {a00, a10};
        ull aH[2] = {a01, a11};

        #pragma unroll
        for (int r = 0; r < 2; r++) {
            const int gr = rb + r0 + r;
            float4 xg = ((const float4*)X)[(size_t)gr*32 + lane];
            float4 hv;
            hv.x = f2lo(aL[r]) + bz.x + xg.x;
            hv.y = f2hi(aL[r]) + bz.y + xg.y;
            hv.z = f2lo(aH[r]) + bz.z + xg.z;
            hv.w = f2hi(aH[r]) + bz.w + xg.w;

            float s  = hv.x + hv.y + hv.z + hv.w;
            float s2 = hv.x*hv.x + hv.y*hv.y + hv.z*hv.z + hv.w*hv.w;
            #pragma unroll
            for (int o = 16; o > 0; o >>= 1) {
                s  += __shfl_xor_sync(0xFFFFFFFFu, s,  o);
                s2 += __shfl_xor_sync(0xFFFFFFFFu, s2, o);
            }
            float mu  = s * (1.f/128.f);
            float var = s2 * (1.f/128.f) - mu*mu;
            float is  = rsqrtf(fmaxf(var, 0.f) + 1e-12f);

            float4 o4;
            o4.x = (hv.x - mu)*is*g.x + bb.x;
            o4.y = (hv.y - mu)*is*g.y + bb.y;
            o4.z = (hv.z - mu)*is*g.z + bb.z;
            o4.w = (hv.w - mu)*is*g.w + bb.w;
            ((float4*)out)[(size_t)gr*32 + lane] = o4;
        }
    }

    // ---- ack + counter reset for next (graph-replayed) launch --------------
    __syncthreads();
    if (tid == 0) {
        __threadfence();
        unsigned v = atomicAdd(&g_bar3, 1u);
        if (v == GRID - 1) {
            *(volatile unsigned*)&g_bar1 = 0;
            *(volatile unsigned*)&g_bar2 = 0;
            *(volatile unsigned*)&g_bar3 = 0;
            __threadfence();
        }
    }
}

// ---------------------------------------------------------------------------
extern "C" void kernel_launch(void* const* d_in, const int* in_sizes, int n_in,
                              void* d_out, int out_size)
{
    const float* X    = (const float*)d_in[0];
    const void*  tsq  = d_in[1];
    const float* mask = (const float*)d_in[2];
    const float* Wq   = (const float*)d_in[3];
    const float* bq   = (const float*)d_in[4];
    const float* Wk   = (const float*)d_in[5];
    const float* bk   = (const float*)d_in[6];
    const float* Wv   = (const float*)d_in[7];
    const float* bv   = (const float*)d_in[8];
    const float* Wd   = (const float*)d_in[9];
    const float* bd   = (const float*)d_in[10];
    const float* lng  = (const float*)d_in[11];
    const float* lnb  = (const float*)d_in[12];
    const float* KT   = (const float*)d_in[13];
    const float* VT   = (const float*)d_in[14];
    const float* kp   = (const float*)d_in[15];
    const float* vp   = (const float*)d_in[16];

    const size_t smem = SMEM_FLOATS * sizeof(float);   // ~163KB -> 1 block/SM

    cudaFuncSetAttribute(fused_kernel, cudaFuncAttributeMaxDynamicSharedMemorySize, (int)smem);

    fused_kernel<<<GRID, 256, smem>>>(X, tsq, mask, Wq, bq, Wk, bk, Wv, bv,
                                      Wd, bd, lng, lnb, KT, VT, kp, vp,
                                      (float*)d_out);
}

// round 15
// speedup vs baseline: 1.0988x; 1.0988x over previous
#include <cuda_runtime.h>
#include <stdint.h>
#include <math.h>

#define HH   128
#define NHD  2
#define HDd  64
#define BB   8
#define LLs  200
#define TVC  32
#define NROWS (BB*LLs)   // 1600
#define KSTR 70          // attn smem row stride (floats): conflict-free

typedef unsigned long long ull;

// scratch (device globals: no allocation allowed)
__device__ float g_q  [NROWS*HH];
__device__ float g_kk [NROWS*HH];
__device__ float g_vv [NROWS*HH];
__device__ float g_ctx[NROWS*HH];

// ---- helpers --------------------------------------------------------------
__device__ __forceinline__ void cp16(uint32_t s, const void* g) {
    asm volatile("cp.async.cg.shared.global [%0], [%1], 16;" :: "r"(s), "l"(g));
}
__device__ __forceinline__ void cp_commit_wait() {
    asm volatile("cp.async.commit_group;");
    asm volatile("cp.async.wait_group 0;" ::: "memory");
}
__device__ __forceinline__ ull pk2(float x) {
    ull r; asm("mov.b64 %0,{%1,%1};" : "=l"(r) : "f"(x)); return r;
}
__device__ __forceinline__ void fma2(ull& d, ull a, ull b) {
    asm("fma.rn.f32x2 %0,%1,%2,%0;" : "+l"(d) : "l"(a), "l"(b));
}
__device__ __forceinline__ float f2lo(ull v) {
    float a, b; asm("mov.b64 {%0,%1},%2;" : "=f"(a), "=f"(b) : "l"(v)); return a;
}
__device__ __forceinline__ float f2hi(ull v) {
    float a, b; asm("mov.b64 {%0,%1},%2;" : "=f"(a), "=f"(b) : "l"(v)); return b;
}

extern __shared__ float smem_dyn[];

// ---------------------------------------------------------------------------
// Kernel 1: fused QKV projection (R10 config — best measured: 8.5us)
// grid (25, 3, 2), block 256.  64 rows x 64 cols per block.
// ---------------------------------------------------------------------------
#define PSTEP8(comp, j)                                                       \
    {                                                                         \
        ull wv = wsu[(i0 + (j))*32 + lane];                                   \
        fma2(acc0, pk2(xr0.comp), wv);                                        \
        fma2(acc1, pk2(xr1.comp), wv);                                        \
        fma2(acc2, pk2(xr2.comp), wv);                                        \
        fma2(acc3, pk2(xr3.comp), wv);                                        \
        fma2(acc4, pk2(xr4.comp), wv);                                        \
        fma2(acc5, pk2(xr5.comp), wv);                                        \
        fma2(acc6, pk2(xr6.comp), wv);                                        \
        fma2(acc7, pk2(xr7.comp), wv);                                        \
    }

__global__ void __launch_bounds__(256, 2)
proj_kernel(const float* __restrict__ X,
            const float* __restrict__ Wq, const float* __restrict__ bq,
            const float* __restrict__ Wk, const float* __restrict__ bk,
            const float* __restrict__ Wv, const float* __restrict__ bv,
            const float* __restrict__ kpos, const float* __restrict__ vpos)
{
    const int m    = blockIdx.y;
    const int hf   = blockIdx.z;
    const int rb   = blockIdx.x * 64;
    const int tid  = threadIdx.x;
    const int lane = tid & 31;
    const int wid  = tid >> 5;

    float* xs = smem_dyn;          // 64*128
    float* ws = smem_dyn + 8192;   // 128*64

    const float* W    = (m==0) ? Wq : (m==1 ? Wk : Wv);
    const float* bias = (m==0) ? bq : (m==1 ? bk : bv);

    {
        uint32_t xs_s = (uint32_t)__cvta_generic_to_shared(xs);
        uint32_t ws_s = (uint32_t)__cvta_generic_to_shared(ws);
        #pragma unroll
        for (int j = 0; j < 8; j++) {
            int c = tid + 256*j;
            cp16(xs_s + c*16, X + (size_t)rb*128 + c*4);
        }
        #pragma unroll
        for (int j = 0; j < 8; j++) {
            int c = tid + 256*j;
            int i = c >> 4, sub = c & 15;
            cp16(ws_s + (i*64 + sub*4)*4, W + i*128 + hf*64 + sub*4);
        }
        cp_commit_wait();
    }
    __syncthreads();

    const int r0 = wid * 8;
    ull acc0=0, acc1=0, acc2=0, acc3=0, acc4=0, acc5=0, acc6=0, acc7=0;
    const ull* wsu = (const ull*)ws;

    for (int i0 = 0; i0 < 128; i0 += 4) {
        float4 xr0 = *(const float4*)(xs + (r0+0)*128 + i0);
        float4 xr1 = *(const float4*)(xs + (r0+1)*128 + i0);
        float4 xr2 = *(const float4*)(xs + (r0+2)*128 + i0);
        float4 xr3 = *(const float4*)(xs + (r0+3)*128 + i0);
        float4 xr4 = *(const float4*)(xs + (r0+4)*128 + i0);
        float4 xr5 = *(const float4*)(xs + (r0+5)*128 + i0);
        float4 xr6 = *(const float4*)(xs + (r0+6)*128 + i0);
        float4 xr7 = *(const float4*)(xs + (r0+7)*128 + i0);
        PSTEP8(x, 0)
        PSTEP8(y, 1)
        PSTEP8(z, 2)
        PSTEP8(w, 3)
    }

    const int col = hf*64 + lane*2;
    float2 bz = *(const float2*)(bias + col);
    float* outg = (m==0) ? g_q : (m==1 ? g_kk : g_vv);
    const float* pos = (m==1) ? kpos : vpos;

    ull acc[8] = {acc0, acc1, acc2, acc3, acc4, acc5, acc6, acc7};
    #pragma unroll
    for (int r = 0; r < 8; r++) {
        const int gr = rb + r0 + r;
        float2 o;
        o.x = f2lo(acc[r]) + bz.x;
        o.y = f2hi(acc[r]) + bz.y;
        if (m != 0) {
            float2 p = *(const float2*)(pos + (gr % LLs)*128 + col);
            o.x += p.x; o.y += p.y;
        }
        *(float2*)(outg + (size_t)gr*128 + col) = o;
    }
}

// ---------------------------------------------------------------------------
// Kernel 2: attention — R7 dataflow (best of 7 variants), with the tid<5
// reduce step replaced by redundant per-thread summation (−1 barrier/iter,
// bit-identical result: same 8-term summation order).
// ---------------------------------------------------------------------------
#define SMEM_FLOATS 40736

__global__ void attn_kernel(const float* __restrict__ maskg,
                            const void*  __restrict__ tsq,
                            const float* __restrict__ KTg,
                            const float* __restrict__ VTg)
{
    float* sm = smem_dyn;
    const int qt   = blockIdx.x;
    const int h    = blockIdx.y;
    const int b    = blockIdx.z;
    const int tid  = threadIdx.x;
    const int lane = tid & 31;
    const int wid  = tid >> 5;

    float* kk    = sm;                   // 200*70
    float* vv    = sm + 14000;           // 200*70
    float* kt    = sm + 28000;           // 32*70
    float* vt    = sm + 30240;           // 32*70
    int*   tv    = (int*)(sm + 32480);   // 200
    float* qall  = sm + 32680;           // 25*64
    float* tsall = sm + 34280;           // 25*32
    float* pdA   = sm + 35080;           // 200 float4
    float* pdB   = sm + 35880;           // 200
    float* sdA   = sm + 36080;           // 200 float4
    float* sdB   = sm + 36880;           // 200
    int*   ix4   = (int*)(sm + 37080);   // 200 int4
    int*   ixb   = (int*)(sm + 37880);   // 200
    float* pA    = sm + 38080;           // 5*8*32 float2
    float* red   = sm + 40640;           // 96

    const float* kkg = g_kk + (size_t)(b*LLs)*HH + h*HDd;
    const float* vvg = g_vv + (size_t)(b*LLs)*HH + h*HDd;
    for (int idx = tid; idx < LLs*32; idx += 256) {
        int k = idx >> 5, d2 = idx & 31;
        ((float2*)(kk + k*KSTR))[d2] = ((const float2*)(kkg + k*HH))[d2];
        ((float2*)(vv + k*KSTR))[d2] = ((const float2*)(vvg + k*HH))[d2];
    }
    for (int idx = tid; idx < TVC*32; idx += 256) {
        int w = idx >> 5, d2 = idx & 31;
        ((float2*)(kt + w*KSTR))[d2] = ((const float2*)(KTg + w*HH + h*HDd))[d2];
        ((float2*)(vt + w*KSTR))[d2] = ((const float2*)(VTg + w*HH + h*HDd))[d2];
    }
    // time values: detect int64 vs int32 storage (word 199 is the high word
    // of element 99 if int64 -> 0; the sorted max of row 0 if int32 -> >0).
    {
        const int* t32 = (const int*)tsq;
        bool is64 = (t32[199] == 0);
        for (int k = tid; k < LLs; k += 256)
            tv[k] = is64 ? (int)((const long long*)tsq)[b*LLs + k]
                         : t32[b*LLs + k];
    }
    {
        const float* qg = g_q + (size_t)(b*LLs)*HH + h*HDd;
        for (int idx = tid; idx < 25*16; idx += 256) {
            int q = idx >> 4, d4 = idx & 15;
            ((float4*)(qall + q*64))[d4] = ((const float4*)(qg + (qt*25+q)*HH))[d4];
        }
    }
    __syncthreads();

    for (int i = tid; i < 25*32; i += 256) {
        int q = i >> 5, w = i & 31;
        const ull* q2  = (const ull*)(qall + q*64);
        const ull* ktr = (const ull*)(kt + w*KSTR);
        ull a = 0;
        #pragma unroll
        for (int j = 0; j < 32; j++) fma2(a, q2[j], ktr[j]);
        tsall[i] = f2lo(a) + f2hi(a);
    }
    __syncthreads();

    for (int it = 0; it < 5; it++) {
        const int q0    = it*5;
        const int qbase = qt*25 + q0;

        float s[5], e[5];
        #pragma unroll
        for (int q = 0; q < 5; q++) { s[q] = -1e30f; e[q] = 0.f; }

        const int k = tid;
        if (k < LLs) {
            ull a2[5];
            #pragma unroll
            for (int q = 0; q < 5; q++) a2[q] = 0;

            const ull* kr = (const ull*)(kk + k*KSTR);
            #pragma unroll
            for (int j = 0; j < 32; j++) {
                ull y = kr[j];
                #pragma unroll
                for (int q = 0; q < 5; q++) {
                    ull x = ((const ull*)(qall + (q0+q)*64))[j];
                    fma2(a2[q], x, y);
                }
            }

            const int tk = tv[k];
            const float* mrow = maskg + ((size_t)(b*LLs) + qbase)*LLs + k;
            int ixs[5];
            #pragma unroll
            for (int q = 0; q < 5; q++) {
                float aq = f2lo(a2[q]) + f2hi(a2[q]);
                int dt = tv[qbase+q] - tk; if (dt < 0) dt = -dt;
                int ixq = (int)log1pf((float)dt);
                s[q] = (aq + tsall[(q0+q)*32 + ixq])*0.125f + mrow[q*LLs];
                ixs[q] = ixq;
            }
            ((int4*)ix4)[k] = make_int4(ixs[0], ixs[1], ixs[2], ixs[3]);
            ixb[k] = ixs[4];
            ((float4*)sdA)[k] = make_float4(s[0], s[1], s[2], s[3]);
            sdB[k] = s[4];
            #pragma unroll
            for (int q = 0; q < 5; q++) e[q] = __expf(s[q]);
        }

        #pragma unroll
        for (int q = 0; q < 5; q++) {
            float se = e[q];
            #pragma unroll
            for (int o = 16; o > 0; o >>= 1)
                se += __shfl_xor_sync(0xFFFFFFFFu, se, o);
            if (lane == 0) red[q*8 + wid] = se;
        }
        __syncthreads();   // B1: e-sum partials + s/ix stores visible

        // every thread computes rs[q] redundantly (same 8-term order ->
        // bit-identical to the old tid<5 path; removes one barrier)
        float rs[5];
        #pragma unroll
        for (int q = 0; q < 5; q++) {
            float se = red[q*8];
            #pragma unroll
            for (int i = 1; i < 8; i++) se += red[q*8 + i];
            rs[q] = 1.f / se;
        }

        if (k < LLs) {
            float4 p;
            p.x = e[0]*rs[0]; p.y = e[1]*rs[1];
            p.z = e[2]*rs[2]; p.w = e[3]*rs[3];
            ((float4*)pdA)[k] = p;
            pdB[k] = e[4]*rs[4];
        }
        __syncthreads();   // B2: pd visible

        {
            const int kc = wid, d2 = lane;
            float2 acc[5];
            #pragma unroll
            for (int q = 0; q < 5; q++) { acc[q].x = 0.f; acc[q].y = 0.f; }
            const int kb = kc*25;
            #pragma unroll 5
            for (int kk2 = 0; kk2 < 25; kk2++) {
                int kx = kb + kk2;
                float2 v  = *(const float2*)(vv + kx*KSTR + 2*d2);
                int4   iv = ((const int4*)ix4)[kx];
                int    i4 = ixb[kx];
                float2 t0 = *(const float2*)(vt + iv.x*KSTR + 2*d2);
                float2 t1 = *(const float2*)(vt + iv.y*KSTR + 2*d2);
                float2 t2 = *(const float2*)(vt + iv.z*KSTR + 2*d2);
                float2 t3 = *(const float2*)(vt + iv.w*KSTR + 2*d2);
                float2 t4 = *(const float2*)(vt + i4*KSTR   + 2*d2);
                float4 p4 = ((const float4*)pdA)[kx];
                float  pb = pdB[kx];
                float4 s4 = ((const float4*)sdA)[kx];
                float  sb = sdB[kx];
                acc[0].x += p4.x*v.x + s4.x*t0.x; acc[0].y += p4.x*v.y + s4.x*t0.y;
                acc[1].x += p4.y*v.x + s4.y*t1.x; acc[1].y += p4.y*v.y + s4.y*t1.y;
                acc[2].x += p4.z*v.x + s4.z*t2.x; acc[2].y += p4.z*v.y + s4.z*t2.y;
                acc[3].x += p4.w*v.x + s4.w*t3.x; acc[3].y += p4.w*v.y + s4.w*t3.y;
                acc[4].x += pb  *v.x + sb  *t4.x; acc[4].y += pb  *v.y + sb  *t4.y;
            }
            #pragma unroll
            for (int q = 0; q < 5; q++)
                ((float2*)pA)[(q*8 + kc)*32 + d2] = acc[q];
        }
        __syncthreads();   // B3: partials visible

        if (tid < 160) {
            int q = tid >> 5, d2 = tid & 31;
            float2 a; a.x = 0.f; a.y = 0.f;
            #pragma unroll
            for (int kc = 0; kc < 8; kc++) {
                float2 x = ((float2*)pA)[(q*8 + kc)*32 + d2];
                a.x += x.x; a.y += x.y;
            }
            *(float2*)(g_ctx + ((size_t)(b*LLs) + qbase + q)*HH + h*HDd + 2*d2) = a;
        }
        __syncthreads();   // B4
    }
}

// ---------------------------------------------------------------------------
// Kernel 3: output projection + bias + residual + LayerNorm (R7 grid-100)
// ---------------------------------------------------------------------------
__global__ void __launch_bounds__(256, 1)
out_ln_kernel(const float* __restrict__ X,
              const float* __restrict__ Wd, const float* __restrict__ bd,
              const float* __restrict__ lng, const float* __restrict__ lnb,
              float* __restrict__ out)
{
    const int rb   = blockIdx.x * 16;
    const int tid  = threadIdx.x;
    const int lane = tid & 31;
    const int wid  = tid >> 5;

    float* xs = smem_dyn;          // 16*128
    float* ws = smem_dyn + 2048;   // 128*128

    {
        uint32_t xs_s = (uint32_t)__cvta_generic_to_shared(xs);
        uint32_t ws_s = (uint32_t)__cvta_generic_to_shared(ws);
        #pragma unroll
        for (int j = 0; j < 2; j++) {
            int c = tid + 256*j;
            cp16(xs_s + c*16, g_ctx + (size_t)rb*128 + c*4);
        }
        #pragma unroll
        for (int j = 0; j < 16; j++) {
            int c = tid + 256*j;
            cp16(ws_s + c*16, Wd + c*4);
        }
        cp_commit_wait();
    }
    __syncthreads();

    const int r0 = wid * 2;
    ull a00=0, a01=0, a10=0, a11=0;
    const ulonglong2* ws2 = (const ulonglong2*)ws;

    #define OSTEP(comp, j)                                                    \
        {                                                                     \
            ulonglong2 wv = ws2[(i0 + (j))*32 + lane];                        \
            ull p0 = pk2(xr0.comp), p1 = pk2(xr1.comp);                       \
            fma2(a00, p0, wv.x); fma2(a01, p0, wv.y);                         \
            fma2(a10, p1, wv.x); fma2(a11, p1, wv.y);                         \
        }

    for (int i0 = 0; i0 < 128; i0 += 4) {
        float4 xr0 = *(const float4*)(xs + (r0+0)*128 + i0);
        float4 xr1 = *(const float4*)(xs + (r0+1)*128 + i0);
        OSTEP(x, 0)
        OSTEP(y, 1)
        OSTEP(z, 2)
        OSTEP(w, 3)
    }
    #undef OSTEP

    float4 bz = ((const float4*)bd)[lane];
    float4 g  = ((const float4*)lng)[lane];
    float4 bb = ((const float4*)lnb)[lane];

    ull aL[2] = {a00, a10};
    ull aH[2] = {a01, a11};

    #pragma unroll
    for (int r = 0; r < 2; r++) {
        const int gr = rb + r0 + r;
        float4 xg = ((const float4*)X)[(size_t)gr*32 + lane];
        float4 hv;
        hv.x = f2lo(aL[r]) + bz.x + xg.x;
        hv.y = f2hi(aL[r]) + bz.y + xg.y;
        hv.z = f2lo(aH[r]) + bz.z + xg.z;
        hv.w = f2hi(aH[r]) + bz.w + xg.w;

        float s  = hv.x + hv.y + hv.z + hv.w;
        float s2 = hv.x*hv.x + hv.y*hv.y + hv.z*hv.z + hv.w*hv.w;
        #pragma unroll
        for (int o = 16; o > 0; o >>= 1) {
            s  += __shfl_xor_sync(0xFFFFFFFFu, s,  o);
            s2 += __shfl_xor_sync(0xFFFFFFFFu, s2, o);
        }
        float mu  = s * (1.f/128.f);
        float var = s2 * (1.f/128.f) - mu*mu;
        float is  = rsqrtf(fmaxf(var, 0.f) + 1e-12f);

        float4 o4;
        o4.x = (hv.x - mu)*is*g.x + bb.x;
        o4.y = (hv.y - mu)*is*g.y + bb.y;
        o4.z = (hv.z - mu)*is*g.z + bb.z;
        o4.w = (hv.w - mu)*is*g.w + bb.w;
        ((float4*)out)[(size_t)gr*32 + lane] = o4;
    }
}

// ---------------------------------------------------------------------------
extern "C" void kernel_launch(void* const* d_in, const int* in_sizes, int n_in,
                              void* d_out, int out_size)
{
    const float* X    = (const float*)d_in[0];
    const void*  tsq  = d_in[1];
    const float* mask = (const float*)d_in[2];
    const float* Wq   = (const float*)d_in[3];
    const float* bq   = (const float*)d_in[4];
    const float* Wk   = (const float*)d_in[5];
    const float* bk   = (const float*)d_in[6];
    const float* Wv   = (const float*)d_in[7];
    const float* bv   = (const float*)d_in[8];
    const float* Wd   = (const float*)d_in[9];
    const float* bd   = (const float*)d_in[10];
    const float* lng  = (const float*)d_in[11];
    const float* lnb  = (const float*)d_in[12];
    const float* KT   = (const float*)d_in[13];
    const float* VT   = (const float*)d_in[14];
    const float* kp   = (const float*)d_in[15];
    const float* vp   = (const float*)d_in[16];

    const size_t smem_proj = (8192 + 8192)  * sizeof(float);  // 64KB
    const size_t smem_out  = (2048 + 16384) * sizeof(float);  // 72KB
    const size_t smem_attn = SMEM_FLOATS * sizeof(float);     // ~163KB

    cudaFuncSetAttribute(proj_kernel,   cudaFuncAttributeMaxDynamicSharedMemorySize, (int)smem_proj);
    cudaFuncSetAttribute(out_ln_kernel, cudaFuncAttributeMaxDynamicSharedMemorySize, (int)smem_out);
    cudaFuncSetAttribute(attn_kernel,   cudaFuncAttributeMaxDynamicSharedMemorySize, (int)smem_attn);

    proj_kernel<<<dim3(25, 3, 2), 256, smem_proj>>>(X, Wq, bq, Wk, bk, Wv, bv, kp, vp);
    attn_kernel<<<dim3(8, NHD, BB), 256, smem_attn>>>(mask, tsq, KT, VT);
    out_ln_kernel<<<100, 256, smem_out>>>(X, Wd, bd, lng, lnb, (float*)d_out);
}